// round 16
// baseline (speedup 1.0000x reference)
#include <cuda_runtime.h>
#include <cstdint>

#define N_PTS 4096
#define DIM   512
#define MARGIN 1.0f
#define NT    (N_PTS / 128)              // 32 tiles per side
#define NBLK  (NT * (NT + 1) / 2)        // 528 upper-triangular tiles
#define INF_F __int_as_float(0x7f800000)

// ---------------- device scratch (no allocations allowed) ----------------
__device__ float         g_sqn[N_PTS];
__device__ unsigned int  g_minsq[N_PTS];   // float bits of masked row-min sq_dist
__device__ double        g_loss_sum;
__device__ unsigned long long g_cnt;
__device__ unsigned long long g_correct;
__device__ unsigned int  g_npairs;
__device__ unsigned int  g_done;
__device__ __align__(16) uint2 g_pairs[1 << 19];       // 4 MB: (anchor i, bits(ap_sq))
// tf32-rounded, fragment-permuted copy of E (A-side layout; B derived by word swap)
__device__ __align__(16) float g_Aperm[N_PTS * DIM];   // 8 MB

// ---------------- PTX helpers (base ISA only, no 'a'-gated features) ----------------
__device__ __forceinline__ uint32_t smem_u32(const void* p) {
    uint32_t a;
    asm("{ .reg .u64 t; cvta.to.shared.u64 t, %1; cvt.u32.u64 %0, t; }" : "=r"(a) : "l"(p));
    return a;
}
#define MBAR_INIT(mb, c)  asm volatile("mbarrier.init.shared.b64 [%0], %1;" :: "r"(mb), "r"(c) : "memory")
#define EXPECT_TX(mb, n)  asm volatile("mbarrier.arrive.expect_tx.shared.b64 _, [%0], %1;" :: "r"(mb), "r"(n) : "memory")
#define BULK_G2S(dst, src, n, mb)                                               \
    asm volatile("cp.async.bulk.shared::cta.global.mbarrier::complete_tx::bytes " \
        "[%0], [%1], %2, [%3];"                                                 \
        :: "r"(dst), "l"(src), "r"(n), "r"(mb) : "memory")
#define NBAR_SYNC(id)   asm volatile("bar.sync %0, 256;"   :: "r"(id) : "memory")
#define NBAR_ARRIVE(id) asm volatile("bar.arrive %0, 256;" :: "r"(id) : "memory")

#define MBAR_WAIT(mb, ph) do {                                                   \
    uint32_t _m = (mb), _p = (ph), _d;                                           \
    asm volatile("{\n\t.reg .pred p;\n\t"                                        \
        "mbarrier.try_wait.parity.acquire.cta.shared::cta.b64 p, [%1], %2;\n\t"  \
        "selp.b32 %0, 1, 0, p;\n\t}" : "=r"(_d) : "r"(_m), "r"(_p) : "memory");  \
    if (!_d) {                                                                   \
        asm volatile("{\n\t.reg .pred P1;\n\t"                                   \
        "WL_%=:\n\t"                                                             \
        "mbarrier.try_wait.parity.acquire.cta.shared::cta.b64 P1, [%0], %1, 0x989680;\n\t" \
        "@P1 bra.uni WD_%=;\n\tbra.uni WL_%=;\n\tWD_%=:\n\t}"                    \
        :: "r"(_m), "r"(_p) : "memory");                                         \
    }                                                                            \
} while (0)

__device__ __forceinline__ void mma_tf32(float* c, const uint32_t* a, uint32_t b0, uint32_t b1) {
    asm volatile("mma.sync.aligned.m16n8k8.row.col.f32.tf32.tf32.f32 "
        "{%0,%1,%2,%3}, {%4,%5,%6,%7}, {%8,%9}, {%0,%1,%2,%3};"
        : "+f"(c[0]), "+f"(c[1]), "+f"(c[2]), "+f"(c[3])
        : "r"(a[0]), "r"(a[1]), "r"(a[2]), "r"(a[3]), "r"(b0), "r"(b1));
}
__device__ __forceinline__ uint32_t to_tf32(float x) {
    uint32_t r;
    asm("cvt.rna.tf32.f32 %0, %1;" : "=r"(r) : "f"(x));
    return r;
}

// ------- kernel 0: tf32 fragment-permute + row sq-norms + scratch reset (merged) -------
// Each thread builds 4 consecutive 16B chunks (lam+0..3, lam%4==0 => same r, j=lam&3):
//   chunk j words: E[r][k0+j], E[r+8][k0+j], E[r][k0+4+j], E[r+8][k0+4+j]
// -> inputs are exactly 4 float4 loads; outputs 4 contiguous uint4 stores.
__global__ __launch_bounds__(256)
void prep_kernel(const float* __restrict__ E) {
    const int t = threadIdx.x;
    if (blockIdx.x == 0 && t == 0) {
        g_npairs = 0u; g_done = 0u;
        g_loss_sum = 0.0; g_cnt = 0ull; g_correct = 0ull;
    }
    // ---- permute part: 4 chunks per thread ----
    {
        const int base = (blockIdx.x * 256 + t) * 4;       // base cid, %4 == 0
        const int lam  = base & 31;                        // 0,4,8,...,28
        const int kk   = (base >> 5) & 3;
        const int G3   = (base >> 7) & 7;
        const int kc   = (base >> 10) & 15;
        const int g8   = base >> 14;
        const int r    = g8 * 128 + G3 * 16 + (lam >> 2);
        const int k0   = kc * 32 + kk * 8;
        const float4 va0 = *reinterpret_cast<const float4*>(E + (size_t)r * DIM + k0);
        const float4 va1 = *reinterpret_cast<const float4*>(E + (size_t)r * DIM + k0 + 4);
        const float4 vb0 = *reinterpret_cast<const float4*>(E + (size_t)(r + 8) * DIM + k0);
        const float4 vb1 = *reinterpret_cast<const float4*>(E + (size_t)(r + 8) * DIM + k0 + 4);
        const float a0[4] = {va0.x, va0.y, va0.z, va0.w};
        const float a1[4] = {va1.x, va1.y, va1.z, va1.w};
        const float b0[4] = {vb0.x, vb0.y, vb0.z, vb0.w};
        const float b1[4] = {vb1.x, vb1.y, vb1.z, vb1.w};
        #pragma unroll
        for (int j = 0; j < 4; j++) {
            reinterpret_cast<uint4*>(g_Aperm)[base + j] =
                make_uint4(to_tf32(a0[j]), to_tf32(b0[j]), to_tf32(a1[j]), to_tf32(b1[j]));
        }
    }
    // ---- sq-norm part: warp-per-row, 8 rows per block ----
    {
        const int lane = t & 31, w = t >> 5;
        const int row  = blockIdx.x * 8 + w;
        float s = 0.0f;
        #pragma unroll
        for (int u = 0; u < 4; u++) {
            float4 v = reinterpret_cast<const float4*>(E + (size_t)row * DIM)[lane + u * 32];
            s += v.x * v.x + v.y * v.y + v.z * v.z + v.w * v.w;
        }
        #pragma unroll
        for (int o = 16; o; o >>= 1) s += __shfl_xor_sync(0xffffffffu, s, o);
        if (lane == 0) {
            g_sqn[row]   = s;
            g_minsq[row] = 0x7f800000u;
        }
    }
}

// ---- kernel 1: tf32 mma GEMM, 128x128 triangular tiles, 3-stage pipeline, 2 CTA/SM ----
// Producer-only sync: consumers bar.arrive (non-blocking) per stage; producer warp
// bar.sync before each refill. 3 named barriers (ids 1..3) track the 3 buffers.
// Epilogue stages sqn/tgt into the (dead) tile buffer ABUF(0) -> LDS not LDG.
// SMEM: [0,24) mbar[3]; [64,576) sminR; [576,1088) sminC; [1088,1096) pcnt/base;
//       [1152,7296) s_pi[1536]; [7296,13440) s_psq[1536]; tiles at 13568.
#define SM_MBAR 0
#define SM_MINR 64
#define SM_MINC 576
#define SM_PCNT 1088
#define SM_PBASE 1092
#define SM_PI   1152
#define SM_PSQ  7296
#define STG_CAP 1536
#define SM_TILE 13568
#define ABUF(s) (SM_TILE + (s) * 32768)
#define BBUF(s) (ABUF(s) + 16384)
#define GEMM_SMEM (SM_TILE + 3 * 32768)

__global__ __launch_bounds__(256, 2)
void gemm_min_kernel(const int* __restrict__ tgt) {
    extern __shared__ char smem[];
    const int tid  = threadIdx.x;
    const int lane = tid & 31;
    const int wid  = tid >> 5;
    const int wm   = wid & 3;     // 4 m-warps (32 rows each)
    const int wn   = wid >> 2;    // 2 n-warps (64 cols each)

    // linear block -> upper-triangular tile (bit <= bjt)
    int kb = blockIdx.x;
    int bjt = (int)((sqrtf(8.0f * (float)kb + 1.0f) - 1.0f) * 0.5f);
    while ((bjt * (bjt + 1)) / 2 > kb) bjt--;
    while (((bjt + 1) * (bjt + 2)) / 2 <= kb) bjt++;
    int bit = kb - (bjt * (bjt + 1)) / 2;
    const int bi = bit * 128;     // rows
    const int bj = bjt * 128;     // cols
    const bool diag = (bit == bjt);

    const uint32_t sb = smem_u32(smem);
    unsigned int* sR  = reinterpret_cast<unsigned int*>(smem + SM_MINR);
    unsigned int* sC  = reinterpret_cast<unsigned int*>(smem + SM_MINC);
    int*      s_pcnt  = reinterpret_cast<int*>(smem + SM_PCNT);
    unsigned* s_pbase = reinterpret_cast<unsigned*>(smem + SM_PBASE);
    unsigned* s_pi    = reinterpret_cast<unsigned*>(smem + SM_PI);
    float*    s_psq   = reinterpret_cast<float*>(smem + SM_PSQ);
    if (tid < 128) { sR[tid] = 0x7f800000u; sC[tid] = 0x7f800000u; }
    if (tid == 0) {
        *s_pcnt = 0;
        MBAR_INIT(sb + SM_MBAR, 1);
        MBAR_INIT(sb + SM_MBAR + 8, 1);
        MBAR_INIT(sb + SM_MBAR + 16, 1);
    }
    __syncthreads();

    const float* gA = g_Aperm + (size_t)bit * 16 * 4096;   // 16 stages x 4096 floats
    const float* gB = g_Aperm + (size_t)bjt * 16 * 4096;
    const uint32_t stage_tx = diag ? 16384u : 32768u;

    if (tid == 224) {
        #pragma unroll
        for (int s0 = 0; s0 < 2; s0++) {               // prefetch stages 0,1
            uint32_t mb = sb + SM_MBAR + 8u * s0;
            EXPECT_TX(mb, stage_tx);
            BULK_G2S(sb + ABUF(s0), gA + (size_t)s0 * 4096, 16384u, mb);
            if (!diag)
                BULK_G2S(sb + BBUF(s0), gB + (size_t)s0 * 4096, 16384u, mb);
        }
    }

    float acc[2][8][4];
    #pragma unroll
    for (int mt = 0; mt < 2; mt++)
        #pragma unroll
        for (int nt = 0; nt < 8; nt++)
            #pragma unroll
            for (int q = 0; q < 4; q++) acc[mt][nt][q] = 0.0f;

    for (int s = 0; s < 16; s++) {
        const int buf = s % 3;
        // Producer warp (wid 7): wait for all consumer arrivals of stage s-1
        // (barrier id (s-1)%3+1) before refilling buffer (s+2)%3 == (s-1)%3.
        if (wid == 7 && s + 2 < 16) {
            if (s >= 1) NBAR_SYNC(((s - 1) % 3) + 1);
            if (tid == 224) {
                const int nb = (s + 2) % 3;
                uint32_t mb = sb + SM_MBAR + 8u * nb;
                EXPECT_TX(mb, stage_tx);
                BULK_G2S(sb + ABUF(nb), gA + (size_t)(s + 2) * 4096, 16384u, mb);
                if (!diag)
                    BULK_G2S(sb + BBUF(nb), gB + (size_t)(s + 2) * 4096, 16384u, mb);
            }
        }
        MBAR_WAIT(sb + SM_MBAR + 8u * buf, (s / 3) & 1);

        const char* Ab = smem + ABUF(buf);
        const char* Bb = diag ? Ab : (smem + BBUF(buf));
        #pragma unroll
        for (int kk = 0; kk < 4; kk++) {
            uint4 a[2], b[4];
            a[0] = *reinterpret_cast<const uint4*>(Ab + (((wm * 2 + 0) * 4 + kk) * 512) + lane * 16);
            a[1] = *reinterpret_cast<const uint4*>(Ab + (((wm * 2 + 1) * 4 + kk) * 512) + lane * 16);
            #pragma unroll
            for (int p = 0; p < 4; p++)
                b[p] = *reinterpret_cast<const uint4*>(Bb + (((wn * 4 + p) * 4 + kk) * 512) + lane * 16);
            #pragma unroll
            for (int mt = 0; mt < 2; mt++) {
                const uint32_t* ar = reinterpret_cast<const uint32_t*>(&a[mt]);
                #pragma unroll
                for (int nt = 0; nt < 8; nt++) {
                    // A-layout words (w00,w10,w01,w11): even sub-col -> (w00,w01), odd -> (w10,w11)
                    const uint32_t* bp = reinterpret_cast<const uint32_t*>(&b[nt >> 1]);
                    uint32_t b0 = (nt & 1) ? bp[1] : bp[0];
                    uint32_t b1 = (nt & 1) ? bp[3] : bp[2];
                    mma_tf32(acc[mt][nt], ar, b0, b1);
                }
            }
        }
        // Consumer warps: non-blocking arrival; phases 0..12 match producer
        // syncs at s=1..13. No arrivals needed for the last 3 stages.
        if (wid != 7 && s <= 12) NBAR_ARRIVE((s % 3) + 1);
    }

    // ---- stage sqn/tgt into the now-dead tile buffer (coalesced LDG -> LDS) ----
    __syncthreads();                                     // tile buffers dead
    float* e_sqi = reinterpret_cast<float*>(smem + ABUF(0));          // [128]
    int*   e_tgi = reinterpret_cast<int*>  (smem + ABUF(0) + 512);    // [128]
    float* e_sqj = reinterpret_cast<float*>(smem + ABUF(0) + 1024);   // [128]
    int*   e_tgj = reinterpret_cast<int*>  (smem + ABUF(0) + 1536);   // [128]
    if (tid < 128) {
        e_sqi[tid] = g_sqn[bi + tid];
        e_tgi[tid] = tgt[bi + tid];
    } else {
        const int u = tid - 128;
        e_sqj[u] = g_sqn[bj + u];
        e_tgj[u] = tgt[bj + u];
    }
    __syncthreads();

    // ---- epilogue: masked min both sides + same-label pair harvest (ballot-free) ----
    const int r0 = lane >> 2;            // 0..7
    const int cb = (lane & 3) * 2;       // 0,2,4,6
    float sqi[4]; int tgi[4]; float sqj[16]; int tgj[16];
    #pragma unroll
    for (int mt = 0; mt < 2; mt++)
        #pragma unroll
        for (int h = 0; h < 2; h++) {
            int rr = wm * 32 + mt * 16 + h * 8 + r0;
            sqi[mt * 2 + h] = e_sqi[rr]; tgi[mt * 2 + h] = e_tgi[rr];
        }
    #pragma unroll
    for (int nt = 0; nt < 8; nt++)
        #pragma unroll
        for (int e = 0; e < 2; e++) {
            int cc = wn * 64 + nt * 8 + cb + e;
            sqj[nt * 2 + e] = e_sqj[cc]; tgj[nt * 2 + e] = e_tgj[cc];
        }
    float rmin[4], cmin[16];
    #pragma unroll
    for (int q = 0; q < 4; q++) rmin[q] = INF_F;
    #pragma unroll
    for (int q = 0; q < 16; q++) cmin[q] = INF_F;

    #pragma unroll
    for (int mt = 0; mt < 2; mt++)
        #pragma unroll
        for (int h = 0; h < 2; h++) {
            const int ri = mt * 2 + h;
            const float si = sqi[ri];
            const int   ti = tgi[ri];
            const int   gi = bi + wm * 32 + mt * 16 + h * 8 + r0;
            #pragma unroll
            for (int nt = 0; nt < 8; nt++)
                #pragma unroll
                for (int e = 0; e < 2; e++) {
                    const int ci = nt * 2 + e;
                    float sq = fmaf(-2.0f, acc[mt][nt][h * 2 + e], si + sqj[ci]);
                    bool samel = (ti == tgj[ci]);
                    if (!samel) {
                        rmin[ri] = fminf(rmin[ri], sq);
                        cmin[ci] = fminf(cmin[ci], sq);
                    } else {
                        const int gj = bj + wn * 64 + nt * 8 + cb + e;
                        if (gi < gj) {
                            int my = atomicAdd(s_pcnt, 1);
                            float sqc = fmaxf(sq, 0.0f);
                            if (my < STG_CAP) { s_pi[my] = (unsigned)gi; s_psq[my] = sqc; }
                            else {
                                unsigned gx = atomicAdd(&g_npairs, 1u);
                                g_pairs[gx] = make_uint2((unsigned)gi, __float_as_uint(sqc));
                            }
                        }
                    }
                }
        }

    #pragma unroll
    for (int mt = 0; mt < 2; mt++)
        #pragma unroll
        for (int h = 0; h < 2; h++)
            atomicMin(&sR[wm * 32 + mt * 16 + h * 8 + r0],
                      __float_as_uint(fmaxf(rmin[mt * 2 + h], 0.0f)));
    #pragma unroll
    for (int nt = 0; nt < 8; nt++)
        #pragma unroll
        for (int e = 0; e < 2; e++)
            atomicMin(&sC[wn * 64 + nt * 8 + cb + e],
                      __float_as_uint(fmaxf(cmin[nt * 2 + e], 0.0f)));
    __syncthreads();

    if (tid < 128) {
        atomicMin(&g_minsq[bi + tid], sR[tid]);
        if (!diag) atomicMin(&g_minsq[bj + tid], sC[tid]);
    }
    if (tid == 0) {
        int c_ = *s_pcnt; c_ = c_ < STG_CAP ? c_ : STG_CAP;
        *s_pbase = atomicAdd(&g_npairs, (unsigned)c_);
    }
    __syncthreads();
    {
        int c_ = *s_pcnt; c_ = c_ < STG_CAP ? c_ : STG_CAP;
        unsigned base = *s_pbase;
        for (int k2 = tid; k2 < c_; k2 += 256)
            g_pairs[base + k2] = make_uint2(s_pi[k2], __float_as_uint(s_psq[k2]));
    }
}

// ---------------- kernel 2: evaluate harvested pairs + last-block finalize ----------------
#define EVAL_BLOCKS 256
__global__ __launch_bounds__(256)
void eval_kernel(float* __restrict__ out, int out_size) {
    const int t = threadIdx.x, lane = t & 31;
    const unsigned n = g_npairs;
    float lsum = 0.0f; int lcnt = 0, lcor = 0;
    for (unsigned idx = blockIdx.x * 256 + t; idx < n; idx += EVAL_BLOCKS * 256) {
        uint2 u = g_pairs[idx];
        float sq = __uint_as_float(u.y);
        float an = __uint_as_float(g_minsq[u.x]);
        if (sqrtf(sq) - sqrtf(an) + MARGIN > 0.0f) {
            lcnt++;
            lsum += fmaxf(sq - an + MARGIN, 0.0f);
            lcor += (sq < an) ? 1 : 0;
        }
    }
    #pragma unroll
    for (int o = 16; o; o >>= 1) {
        lsum += __shfl_xor_sync(0xffffffffu, lsum, o);
        lcnt += __shfl_xor_sync(0xffffffffu, lcnt, o);
        lcor += __shfl_xor_sync(0xffffffffu, lcor, o);
    }
    __shared__ double wsum[8];
    __shared__ int    wcnt[8], wcor[8];
    if (lane == 0) { wsum[t >> 5] = (double)lsum; wcnt[t >> 5] = lcnt; wcor[t >> 5] = lcor; }
    __syncthreads();
    if (t == 0) {
        double bs = 0.0; int bc = 0, br = 0;
        #pragma unroll
        for (int w = 0; w < 8; w++) { bs += wsum[w]; bc += wcnt[w]; br += wcor[w]; }
        if (bc > 0) {
            atomicAdd(&g_loss_sum, bs);
            atomicAdd(&g_cnt, (unsigned long long)bc);
            atomicAdd(&g_correct, (unsigned long long)br);
        }
        __threadfence();
        unsigned d = atomicAdd(&g_done, 1u);
        if (d == EVAL_BLOCKS - 1) {                    // last block finalizes
            unsigned long long c = g_cnt;
            double denom = (double)(c > 0ull ? c : 1ull);
            if (out_size >= 1) out[0] = (float)(g_loss_sum / denom);
            if (out_size >= 2) out[1] = (float)((double)g_correct / denom);
        }
    }
}

// ---------------- launch ----------------
extern "C" void kernel_launch(void* const* d_in, const int* in_sizes, int n_in,
                              void* d_out, int out_size) {
    const float* E;
    const int*   tgt;
    if (in_sizes[0] == N_PTS * DIM) {
        E = (const float*)d_in[0]; tgt = (const int*)d_in[1];
    } else {
        E = (const float*)d_in[1]; tgt = (const int*)d_in[0];
    }

    cudaFuncSetAttribute(gemm_min_kernel,
                         cudaFuncAttributeMaxDynamicSharedMemorySize, GEMM_SMEM);

    prep_kernel<<<N_PTS / 8, 256>>>(E);     // 512 blocks: 4 chunks/thread, 8 sqnorm rows/block

    gemm_min_kernel<<<NBLK, 256, GEMM_SMEM>>>(tgt);

    eval_kernel<<<EVAL_BLOCKS, 256>>>((float*)d_out, out_size);
}

// round 17
// speedup vs baseline: 1.0329x; 1.0329x over previous
#include <cuda_runtime.h>
#include <cstdint>

#define N_PTS 4096
#define DIM   512
#define MARGIN 1.0f
#define NT    (N_PTS / 128)              // 32 tiles per side
#define NBLK  (NT * (NT + 1) / 2)        // 528 upper-triangular tiles
#define INF_F __int_as_float(0x7f800000)

// ---------------- device scratch (no allocations allowed) ----------------
__device__ float         g_sqn[N_PTS];
__device__ unsigned int  g_minsq[N_PTS];   // float bits of masked row-min sq_dist
__device__ double        g_loss_sum;
__device__ unsigned long long g_cnt;
__device__ unsigned long long g_correct;
__device__ unsigned int  g_npairs;
__device__ unsigned int  g_done;
__device__ __align__(16) uint2 g_pairs[1 << 19];       // 4 MB: (anchor i, bits(ap_sq))
// tf32-rounded, fragment-permuted copy of E (A-side layout; B derived by word swap)
__device__ __align__(16) float g_Aperm[N_PTS * DIM];   // 8 MB

// ---------------- PTX helpers (base ISA only, no 'a'-gated features) ----------------
__device__ __forceinline__ uint32_t smem_u32(const void* p) {
    uint32_t a;
    asm("{ .reg .u64 t; cvta.to.shared.u64 t, %1; cvt.u32.u64 %0, t; }" : "=r"(a) : "l"(p));
    return a;
}
#define MBAR_INIT(mb, c)  asm volatile("mbarrier.init.shared.b64 [%0], %1;" :: "r"(mb), "r"(c) : "memory")
#define EXPECT_TX(mb, n)  asm volatile("mbarrier.arrive.expect_tx.shared.b64 _, [%0], %1;" :: "r"(mb), "r"(n) : "memory")
#define BULK_G2S(dst, src, n, mb)                                               \
    asm volatile("cp.async.bulk.shared::cta.global.mbarrier::complete_tx::bytes " \
        "[%0], [%1], %2, [%3];"                                                 \
        :: "r"(dst), "l"(src), "r"(n), "r"(mb) : "memory")
#define NBAR_SYNC(id)   asm volatile("bar.sync %0, 256;"   :: "r"(id) : "memory")
#define NBAR_ARRIVE(id) asm volatile("bar.arrive %0, 256;" :: "r"(id) : "memory")

#define MBAR_WAIT(mb, ph) do {                                                   \
    uint32_t _m = (mb), _p = (ph), _d;                                           \
    asm volatile("{\n\t.reg .pred p;\n\t"                                        \
        "mbarrier.try_wait.parity.acquire.cta.shared::cta.b64 p, [%1], %2;\n\t"  \
        "selp.b32 %0, 1, 0, p;\n\t}" : "=r"(_d) : "r"(_m), "r"(_p) : "memory");  \
    if (!_d) {                                                                   \
        asm volatile("{\n\t.reg .pred P1;\n\t"                                   \
        "WL_%=:\n\t"                                                             \
        "mbarrier.try_wait.parity.acquire.cta.shared::cta.b64 P1, [%0], %1, 0x989680;\n\t" \
        "@P1 bra.uni WD_%=;\n\tbra.uni WL_%=;\n\tWD_%=:\n\t}"                    \
        :: "r"(_m), "r"(_p) : "memory");                                         \
    }                                                                            \
} while (0)

__device__ __forceinline__ void mma_tf32(float* c, const uint32_t* a, uint32_t b0, uint32_t b1) {
    asm volatile("mma.sync.aligned.m16n8k8.row.col.f32.tf32.tf32.f32 "
        "{%0,%1,%2,%3}, {%4,%5,%6,%7}, {%8,%9}, {%0,%1,%2,%3};"
        : "+f"(c[0]), "+f"(c[1]), "+f"(c[2]), "+f"(c[3])
        : "r"(a[0]), "r"(a[1]), "r"(a[2]), "r"(a[3]), "r"(b0), "r"(b1));
}
__device__ __forceinline__ uint32_t to_tf32(float x) {
    uint32_t r;
    asm("cvt.rna.tf32.f32 %0, %1;" : "=r"(r) : "f"(x));
    return r;
}

// ------- kernel 0: tf32 fragment-permute + row sq-norms + scratch reset (merged) -------
//   lam=cid&31, kk=(cid>>5)&3, G3=(cid>>7)&7, kc=(cid>>10)&15, g8=cid>>14
//   r = g8*128 + G3*16 + (lam>>2);  k = kc*32 + kk*8 + (lam&3)
// A words: E[r][k], E[r+8][k], E[r][k+4], E[r+8][k+4]
__global__ __launch_bounds__(256)
void prep_kernel(const float* __restrict__ E) {
    const int t   = threadIdx.x;
    const int cid = blockIdx.x * 256 + t;              // 0 .. 524287
    if (cid == 0) {
        g_npairs = 0u; g_done = 0u;
        g_loss_sum = 0.0; g_cnt = 0ull; g_correct = 0ull;
    }
    // ---- permute part ----
    {
        int lam = cid & 31;
        int kk  = (cid >> 5) & 3;
        int G3  = (cid >> 7) & 7;
        int kc  = (cid >> 10) & 15;
        int g8  = cid >> 14;
        int r   = g8 * 128 + G3 * 16 + (lam >> 2);
        int k   = kc * 32 + kk * 8 + (lam & 3);
        uint32_t w00 = to_tf32(E[(size_t)r * DIM + k]);
        uint32_t w10 = to_tf32(E[(size_t)(r + 8) * DIM + k]);
        uint32_t w01 = to_tf32(E[(size_t)r * DIM + k + 4]);
        uint32_t w11 = to_tf32(E[(size_t)(r + 8) * DIM + k + 4]);
        reinterpret_cast<uint4*>(g_Aperm)[cid] = make_uint4(w00, w10, w01, w11);
    }
    // ---- sq-norm part: rows 2b and 2b+1 ----
    {
        const int row = blockIdx.x * 2 + (t >> 7);
        const int li  = t & 127;
        float4 v = reinterpret_cast<const float4*>(E + (size_t)row * DIM)[li];
        float s = v.x * v.x + v.y * v.y + v.z * v.z + v.w * v.w;
        #pragma unroll
        for (int o = 16; o; o >>= 1) s += __shfl_xor_sync(0xffffffffu, s, o);
        __shared__ float ws[8];
        if ((t & 31) == 0) ws[t >> 5] = s;
        __syncthreads();
        if (t == 0)   g_sqn[row] = ws[0] + ws[1] + ws[2] + ws[3];
        if (t == 128) g_sqn[row] = ws[4] + ws[5] + ws[6] + ws[7];
        if (t < 2)    g_minsq[blockIdx.x * 2 + t] = 0x7f800000u;
    }
}

// ---- kernel 1: tf32 mma GEMM, 128x128 triangular tiles, 3-stage pipeline, 2 CTA/SM ----
// Producer-only sync: consumers bar.arrive (non-blocking) per stage; producer warp
// bar.sync before each refill. 3 named barriers (ids 1..3) track the 3 buffers.
// Epilogue sqn/tgt loaded into REGISTERS at kernel start (read-only during GEMM),
// stored to the dead tile buffer ABUF(0) after the mainloop -> LDS-only epilogue.
// SMEM: [0,24) mbar[3]; [64,576) sminR; [576,1088) sminC; [1088,1096) pcnt/base;
//       [1152,7296) s_pi[1536]; [7296,13440) s_psq[1536]; tiles at 13568.
#define SM_MBAR 0
#define SM_MINR 64
#define SM_MINC 576
#define SM_PCNT 1088
#define SM_PBASE 1092
#define SM_PI   1152
#define SM_PSQ  7296
#define STG_CAP 1536
#define SM_TILE 13568
#define ABUF(s) (SM_TILE + (s) * 32768)
#define BBUF(s) (ABUF(s) + 16384)
#define GEMM_SMEM (SM_TILE + 3 * 32768)

__global__ __launch_bounds__(256, 2)
void gemm_min_kernel(const int* __restrict__ tgt) {
    extern __shared__ char smem[];
    const int tid  = threadIdx.x;
    const int lane = tid & 31;
    const int wid  = tid >> 5;
    const int wm   = wid & 3;     // 4 m-warps (32 rows each)
    const int wn   = wid >> 2;    // 2 n-warps (64 cols each)

    // linear block -> upper-triangular tile (bit <= bjt)
    int kb = blockIdx.x;
    int bjt = (int)((sqrtf(8.0f * (float)kb + 1.0f) - 1.0f) * 0.5f);
    while ((bjt * (bjt + 1)) / 2 > kb) bjt--;
    while (((bjt + 1) * (bjt + 2)) / 2 <= kb) bjt++;
    int bit = kb - (bjt * (bjt + 1)) / 2;
    const int bi = bit * 128;     // rows
    const int bj = bjt * 128;     // cols
    const bool diag = (bit == bjt);

    const uint32_t sb = smem_u32(smem);
    unsigned int* sR  = reinterpret_cast<unsigned int*>(smem + SM_MINR);
    unsigned int* sC  = reinterpret_cast<unsigned int*>(smem + SM_MINC);
    int*      s_pcnt  = reinterpret_cast<int*>(smem + SM_PCNT);
    unsigned* s_pbase = reinterpret_cast<unsigned*>(smem + SM_PBASE);
    unsigned* s_pi    = reinterpret_cast<unsigned*>(smem + SM_PI);
    float*    s_psq   = reinterpret_cast<float*>(smem + SM_PSQ);
    if (tid < 128) { sR[tid] = 0x7f800000u; sC[tid] = 0x7f800000u; }
    if (tid == 0) {
        *s_pcnt = 0;
        MBAR_INIT(sb + SM_MBAR, 1);
        MBAR_INIT(sb + SM_MBAR + 8, 1);
        MBAR_INIT(sb + SM_MBAR + 16, 1);
    }
    __syncthreads();

    // Early issue of epilogue data (read-only during GEMM): 2 coalesced loads,
    // held in registers across the mainloop, stored to smem afterwards.
    float my_sq;
    int   my_tg;
    {
        const int src = (tid < 128) ? (bi + tid) : (bj + tid - 128);
        my_sq = g_sqn[src];
        my_tg = tgt[src];
    }

    const float* gA = g_Aperm + (size_t)bit * 16 * 4096;   // 16 stages x 4096 floats
    const float* gB = g_Aperm + (size_t)bjt * 16 * 4096;
    const uint32_t stage_tx = diag ? 16384u : 32768u;

    if (tid == 224) {
        #pragma unroll
        for (int s0 = 0; s0 < 2; s0++) {               // prefetch stages 0,1
            uint32_t mb = sb + SM_MBAR + 8u * s0;
            EXPECT_TX(mb, stage_tx);
            BULK_G2S(sb + ABUF(s0), gA + (size_t)s0 * 4096, 16384u, mb);
            if (!diag)
                BULK_G2S(sb + BBUF(s0), gB + (size_t)s0 * 4096, 16384u, mb);
        }
    }

    float acc[2][8][4];
    #pragma unroll
    for (int mt = 0; mt < 2; mt++)
        #pragma unroll
        for (int nt = 0; nt < 8; nt++)
            #pragma unroll
            for (int q = 0; q < 4; q++) acc[mt][nt][q] = 0.0f;

    for (int s = 0; s < 16; s++) {
        const int buf = s % 3;
        // Producer warp (wid 7): wait for all consumer arrivals of stage s-1
        // (barrier id (s-1)%3+1) before refilling buffer (s+2)%3 == (s-1)%3.
        if (wid == 7 && s + 2 < 16) {
            if (s >= 1) NBAR_SYNC(((s - 1) % 3) + 1);
            if (tid == 224) {
                const int nb = (s + 2) % 3;
                uint32_t mb = sb + SM_MBAR + 8u * nb;
                EXPECT_TX(mb, stage_tx);
                BULK_G2S(sb + ABUF(nb), gA + (size_t)(s + 2) * 4096, 16384u, mb);
                if (!diag)
                    BULK_G2S(sb + BBUF(nb), gB + (size_t)(s + 2) * 4096, 16384u, mb);
            }
        }
        MBAR_WAIT(sb + SM_MBAR + 8u * buf, (s / 3) & 1);

        const char* Ab = smem + ABUF(buf);
        const char* Bb = diag ? Ab : (smem + BBUF(buf));
        #pragma unroll
        for (int kk = 0; kk < 4; kk++) {
            uint4 a[2], b[4];
            a[0] = *reinterpret_cast<const uint4*>(Ab + (((wm * 2 + 0) * 4 + kk) * 512) + lane * 16);
            a[1] = *reinterpret_cast<const uint4*>(Ab + (((wm * 2 + 1) * 4 + kk) * 512) + lane * 16);
            #pragma unroll
            for (int p = 0; p < 4; p++)
                b[p] = *reinterpret_cast<const uint4*>(Bb + (((wn * 4 + p) * 4 + kk) * 512) + lane * 16);
            #pragma unroll
            for (int mt = 0; mt < 2; mt++) {
                const uint32_t* ar = reinterpret_cast<const uint32_t*>(&a[mt]);
                #pragma unroll
                for (int nt = 0; nt < 8; nt++) {
                    // A-layout words (w00,w10,w01,w11): even sub-col -> (w00,w01), odd -> (w10,w11)
                    const uint32_t* bp = reinterpret_cast<const uint32_t*>(&b[nt >> 1]);
                    uint32_t b0 = (nt & 1) ? bp[1] : bp[0];
                    uint32_t b1 = (nt & 1) ? bp[3] : bp[2];
                    mma_tf32(acc[mt][nt], ar, b0, b1);
                }
            }
        }
        // Consumer warps: non-blocking arrival; phases 0..12 match producer
        // syncs at s=1..13. No arrivals needed for the last 3 stages.
        if (wid != 7 && s <= 12) NBAR_ARRIVE((s % 3) + 1);
    }

    // ---- store register-held sqn/tgt into the now-dead tile buffer (STS only) ----
    __syncthreads();                                     // tile buffers dead
    float* e_sqi = reinterpret_cast<float*>(smem + ABUF(0));          // [128]
    int*   e_tgi = reinterpret_cast<int*>  (smem + ABUF(0) + 512);    // [128]
    float* e_sqj = reinterpret_cast<float*>(smem + ABUF(0) + 1024);   // [128]
    int*   e_tgj = reinterpret_cast<int*>  (smem + ABUF(0) + 1536);   // [128]
    if (tid < 128) {
        e_sqi[tid] = my_sq;
        e_tgi[tid] = my_tg;
    } else {
        const int u = tid - 128;
        e_sqj[u] = my_sq;
        e_tgj[u] = my_tg;
    }
    __syncthreads();

    // ---- epilogue: masked min both sides + same-label pair harvest (ballot-free) ----
    const int r0 = lane >> 2;            // 0..7
    const int cb = (lane & 3) * 2;       // 0,2,4,6
    float sqi[4]; int tgi[4]; float sqj[16]; int tgj[16];
    #pragma unroll
    for (int mt = 0; mt < 2; mt++)
        #pragma unroll
        for (int h = 0; h < 2; h++) {
            int rr = wm * 32 + mt * 16 + h * 8 + r0;
            sqi[mt * 2 + h] = e_sqi[rr]; tgi[mt * 2 + h] = e_tgi[rr];
        }
    #pragma unroll
    for (int nt = 0; nt < 8; nt++)
        #pragma unroll
        for (int e = 0; e < 2; e++) {
            int cc = wn * 64 + nt * 8 + cb + e;
            sqj[nt * 2 + e] = e_sqj[cc]; tgj[nt * 2 + e] = e_tgj[cc];
        }
    float rmin[4], cmin[16];
    #pragma unroll
    for (int q = 0; q < 4; q++) rmin[q] = INF_F;
    #pragma unroll
    for (int q = 0; q < 16; q++) cmin[q] = INF_F;

    #pragma unroll
    for (int mt = 0; mt < 2; mt++)
        #pragma unroll
        for (int h = 0; h < 2; h++) {
            const int ri = mt * 2 + h;
            const float si = sqi[ri];
            const int   ti = tgi[ri];
            const int   gi = bi + wm * 32 + mt * 16 + h * 8 + r0;
            #pragma unroll
            for (int nt = 0; nt < 8; nt++)
                #pragma unroll
                for (int e = 0; e < 2; e++) {
                    const int ci = nt * 2 + e;
                    float sq = fmaf(-2.0f, acc[mt][nt][h * 2 + e], si + sqj[ci]);
                    bool samel = (ti == tgj[ci]);
                    if (!samel) {
                        rmin[ri] = fminf(rmin[ri], sq);
                        cmin[ci] = fminf(cmin[ci], sq);
                    } else {
                        const int gj = bj + wn * 64 + nt * 8 + cb + e;
                        if (gi < gj) {
                            int my = atomicAdd(s_pcnt, 1);
                            float sqc = fmaxf(sq, 0.0f);
                            if (my < STG_CAP) { s_pi[my] = (unsigned)gi; s_psq[my] = sqc; }
                            else {
                                unsigned gx = atomicAdd(&g_npairs, 1u);
                                g_pairs[gx] = make_uint2((unsigned)gi, __float_as_uint(sqc));
                            }
                        }
                    }
                }
        }

    #pragma unroll
    for (int mt = 0; mt < 2; mt++)
        #pragma unroll
        for (int h = 0; h < 2; h++)
            atomicMin(&sR[wm * 32 + mt * 16 + h * 8 + r0],
                      __float_as_uint(fmaxf(rmin[mt * 2 + h], 0.0f)));
    #pragma unroll
    for (int nt = 0; nt < 8; nt++)
        #pragma unroll
        for (int e = 0; e < 2; e++)
            atomicMin(&sC[wn * 64 + nt * 8 + cb + e],
                      __float_as_uint(fmaxf(cmin[nt * 2 + e], 0.0f)));
    __syncthreads();

    if (tid < 128) {
        atomicMin(&g_minsq[bi + tid], sR[tid]);
        if (!diag) atomicMin(&g_minsq[bj + tid], sC[tid]);
    }
    if (tid == 0) {
        int c_ = *s_pcnt; c_ = c_ < STG_CAP ? c_ : STG_CAP;
        *s_pbase = atomicAdd(&g_npairs, (unsigned)c_);
    }
    __syncthreads();
    {
        int c_ = *s_pcnt; c_ = c_ < STG_CAP ? c_ : STG_CAP;
        unsigned base = *s_pbase;
        for (int k2 = tid; k2 < c_; k2 += 256)
            g_pairs[base + k2] = make_uint2(s_pi[k2], __float_as_uint(s_psq[k2]));
    }
}

// ---------------- kernel 2: evaluate harvested pairs + last-block finalize ----------------
#define EVAL_BLOCKS 256
__global__ __launch_bounds__(256)
void eval_kernel(float* __restrict__ out, int out_size) {
    const int t = threadIdx.x, lane = t & 31;
    const unsigned n = g_npairs;
    float lsum = 0.0f; int lcnt = 0, lcor = 0;
    for (unsigned idx = blockIdx.x * 256 + t; idx < n; idx += EVAL_BLOCKS * 256) {
        uint2 u = g_pairs[idx];
        float sq = __uint_as_float(u.y);
        float an = __uint_as_float(g_minsq[u.x]);
        if (sqrtf(sq) - sqrtf(an) + MARGIN > 0.0f) {
            lcnt++;
            lsum += fmaxf(sq - an + MARGIN, 0.0f);
            lcor += (sq < an) ? 1 : 0;
        }
    }
    #pragma unroll
    for (int o = 16; o; o >>= 1) {
        lsum += __shfl_xor_sync(0xffffffffu, lsum, o);
        lcnt += __shfl_xor_sync(0xffffffffu, lcnt, o);
        lcor += __shfl_xor_sync(0xffffffffu, lcor, o);
    }
    __shared__ double wsum[8];
    __shared__ int    wcnt[8], wcor[8];
    if (lane == 0) { wsum[t >> 5] = (double)lsum; wcnt[t >> 5] = lcnt; wcor[t >> 5] = lcor; }
    __syncthreads();
    if (t == 0) {
        double bs = 0.0; int bc = 0, br = 0;
        #pragma unroll
        for (int w = 0; w < 8; w++) { bs += wsum[w]; bc += wcnt[w]; br += wcor[w]; }
        if (bc > 0) {
            atomicAdd(&g_loss_sum, bs);
            atomicAdd(&g_cnt, (unsigned long long)bc);
            atomicAdd(&g_correct, (unsigned long long)br);
        }
        __threadfence();
        unsigned d = atomicAdd(&g_done, 1u);
        if (d == EVAL_BLOCKS - 1) {                    // last block finalizes
            unsigned long long c = g_cnt;
            double denom = (double)(c > 0ull ? c : 1ull);
            if (out_size >= 1) out[0] = (float)(g_loss_sum / denom);
            if (out_size >= 2) out[1] = (float)((double)g_correct / denom);
        }
    }
}

// ---------------- launch ----------------
extern "C" void kernel_launch(void* const* d_in, const int* in_sizes, int n_in,
                              void* d_out, int out_size) {
    const float* E;
    const int*   tgt;
    if (in_sizes[0] == N_PTS * DIM) {
        E = (const float*)d_in[0]; tgt = (const int*)d_in[1];
    } else {
        E = (const float*)d_in[1]; tgt = (const int*)d_in[0];
    }

    cudaFuncSetAttribute(gemm_min_kernel,
                         cudaFuncAttributeMaxDynamicSharedMemorySize, GEMM_SMEM);

    prep_kernel<<<N_PTS / 2, 256>>>(E);

    gemm_min_kernel<<<NBLK, 256, GEMM_SMEM>>>(tgt);

    eval_kernel<<<EVAL_BLOCKS, 256>>>((float*)d_out, out_size);
}